// round 14
// baseline (speedup 1.0000x reference)
#include <cuda_runtime.h>
#include <cstdint>
#include <mma.h>

using namespace nvcuda;

#define NNODES 100000
#define NEDGES 1600000
#define DIN 256
#define DH 128
#define DOUT 64
#define BN_EPS 1e-5f
#define NB_SCAN 391   // ceil(100000/256)
#define AGG_BLOCKS 1024

// ---------------- static device scratch ----------------
__device__ float g_dinv[NNODES];
__device__ int   g_deg[NNODES];
__device__ int   g_cursor[NNODES];
__device__ int   g_rowptr[NNODES + 1];
__device__ int   g_bsum[512];
__device__ int   g_col[NEDGES];
__device__ float g_wgt[NEDGES];
__device__ float g_H [NNODES * DH];   // GEMM output (XW)
__device__ float g_A [NNODES * DH];   // aggregated conv output (pre-BN)
__device__ float g_stats[2 * DH];     // column sums / sumsq
__device__ float g_scale[DH];
__device__ float g_shift[DH];

// ---------------- cp.async helpers ----------------
__device__ __forceinline__ unsigned smem_u32(const void* p) {
    unsigned a;
    asm("{ .reg .u64 t; cvta.to.shared.u64 t, %1; cvt.u32.u64 %0, t; }"
        : "=r"(a) : "l"(p));
    return a;
}
__device__ __forceinline__ void cp_async16(unsigned dst, const void* src, int srcBytes) {
    asm volatile("cp.async.cg.shared.global [%0], [%1], 16, %2;"
                 :: "r"(dst), "l"(src), "r"(srcBytes) : "memory");
}
#define CP_COMMIT() asm volatile("cp.async.commit_group;" ::: "memory")
#define CP_WAIT0()  asm volatile("cp.async.wait_group 0;" ::: "memory")

// ---------------- setup kernels ----------------
__global__ void k_zero_node_ints() {
    int i = blockIdx.x * blockDim.x + threadIdx.x;
    if (i < NNODES) { g_deg[i] = 0; g_cursor[i] = 0; }
    if (i < 2 * DH) g_stats[i] = 0.f;      // initial zero for layer-1 stats
}

__global__ void k_count_deg(const int* __restrict__ ei, int E) {
    int e = blockIdx.x * blockDim.x + threadIdx.x;
    if (e < E) atomicAdd(&g_deg[ei[E + e]], 1);
}

__global__ void k_dinv() {
    int i = blockIdx.x * blockDim.x + threadIdx.x;
    if (i < NNODES) g_dinv[i] = rsqrtf((float)(g_deg[i] + 1));
}

// ---- multi-block exclusive scan: deg -> rowptr ----
__global__ void k_scan1() {
    __shared__ int s[256];
    int t = threadIdx.x;
    int i = blockIdx.x * 256 + t;
    int v = (i < NNODES) ? g_deg[i] : 0;
    s[t] = v;
    __syncthreads();
#pragma unroll
    for (int off = 128; off > 0; off >>= 1) {
        if (t < off) s[t] += s[t + off];
        __syncthreads();
    }
    if (t == 0) g_bsum[blockIdx.x] = s[0];
}

__global__ void k_scan2() {
    __shared__ int s[512];
    int t = threadIdx.x;
    int v = (t < NB_SCAN) ? g_bsum[t] : 0;
    s[t] = v;
    __syncthreads();
    for (int off = 1; off < 512; off <<= 1) {
        int a = (t >= off) ? s[t - off] : 0;
        __syncthreads();
        s[t] += a;
        __syncthreads();
    }
    g_bsum[t] = s[t] - v;                 // exclusive
}

__global__ void k_scan3(int E) {
    __shared__ int s[256];
    int t = threadIdx.x;
    int i = blockIdx.x * 256 + t;
    int v = (i < NNODES) ? g_deg[i] : 0;
    s[t] = v;
    __syncthreads();
    for (int off = 1; off < 256; off <<= 1) {
        int a = (t >= off) ? s[t - off] : 0;
        __syncthreads();
        s[t] += a;
        __syncthreads();
    }
    if (i < NNODES) g_rowptr[i] = g_bsum[blockIdx.x] + s[t] - v;
    if (i == 0) g_rowptr[NNODES] = E;
}

__global__ void k_scatter(const int* __restrict__ ei, int E) {
    int e = blockIdx.x * blockDim.x + threadIdx.x;
    if (e >= E) return;
    int s = ei[e];
    int d = ei[E + e];
    int pos = g_rowptr[d] + atomicAdd(&g_cursor[d], 1);
    g_col[pos] = s;
    g_wgt[pos] = g_dinv[s] * g_dinv[d];
}

// ---------------- WMMA TF32 GEMM with cp.async staging ----------------
// C(g_H)[M x BN] = op(A)[M x K] @ B[K x BN]
// FUSE=false: A = Aext;  FUSE=true: A = relu(g_A*scale[k]+shift[k])
// Pipeline per K-tile: wait(raw) -> transform raw->sA/sB (tf32+FUSE) ->
// issue cp.async for next tile -> mma (copy overlaps mma). Each thread
// consumes exactly the raw chunks it copied, so per-thread wait suffices.
template <int BN, bool FUSE>
__global__ void __launch_bounds__(256)
k_gemm_wmma(const float* __restrict__ Aext, const float* __restrict__ B, int M, int K) {
    constexpr int BM = 128, BK = 32;
    constexpr int SAP = 40;
    constexpr int SBP = BN + 8;
    constexpr int WROWS = 4, WCOLS = 2;
    constexpr int WM = BM / WROWS;       // 32
    constexpr int WN = BN / WCOLS;       // 64 or 32
    constexpr int MT = WM / 16;          // 2
    constexpr int NT = WN / 16;          // 4 or 2
    constexpr int NPB = (BK * BN / 4) / 256;   // B float4 chunks per thread

    extern __shared__ __align__(16) float smem[];
    float* sA   = smem;                  // BM*SAP
    float* sB   = sA + BM * SAP;         // BK*SBP
    float* rawA = sB + BK * SBP;         // BM*BK
    float* rawB = rawA + BM * BK;        // BK*BN

    const unsigned rawA_u = smem_u32(rawA);
    const unsigned rawB_u = smem_u32(rawB);

    const float* A = FUSE ? (const float*)g_A : Aext;   // device-side select

    const int tid = threadIdx.x;
    const int wid = tid >> 5;
    const int wm = wid / WCOLS;
    const int wn = wid % WCOLS;
    const int row0 = blockIdx.x * BM;

    wmma::fragment<wmma::accumulator, 16, 16, 8, float> acc[MT][NT];
#pragma unroll
    for (int i = 0; i < MT; i++)
#pragma unroll
        for (int j = 0; j < NT; j++) wmma::fill_fragment(acc[i][j], 0.0f);

    // ---- issue helpers ----
    auto issueA = [&](int kt) {
#pragma unroll
        for (int p = 0; p < 4; p++) {
            int idx = tid + p * 256;
            int r = idx >> 3;
            int c4 = idx & 7;
            int gr = row0 + r;
            int ok = (gr < M) ? 16 : 0;
            int grc = (gr < M) ? gr : (M - 1);
            cp_async16(rawA_u + (unsigned)idx * 16u,
                       A + (size_t)grc * K + kt + c4 * 4, ok);
        }
    };
    auto issueB = [&](int kt) {
#pragma unroll
        for (int p = 0; p < NPB; p++) {
            int idx = tid + p * 256;
            int r = idx / (BN / 4);
            int c4 = idx % (BN / 4);
            cp_async16(rawB_u + (unsigned)idx * 16u,
                       B + (size_t)(kt + r) * BN + c4 * 4, 16);
        }
    };

    issueA(0);
    issueB(0);
    CP_COMMIT();

    for (int kt = 0; kt < K; kt += BK) {
        CP_WAIT0();                 // own raw chunks for tile kt have landed
        __syncthreads();            // all warps done with previous mma (sA/sB free)

        // ---- transform raw -> sA (FUSE + tf32 cvt + padded layout) ----
#pragma unroll
        for (int p = 0; p < 4; p++) {
            int idx = tid + p * 256;
            int r = idx >> 3;
            int c4 = idx & 7;
            float4 v = ((const float4*)rawA)[idx];
            if (FUSE) {
                float4 sc = *(const float4*)(g_scale + kt + c4 * 4);
                float4 sh = *(const float4*)(g_shift + kt + c4 * 4);
                v.x = fmaxf(0.f, v.x * sc.x + sh.x);
                v.y = fmaxf(0.f, v.y * sc.y + sh.y);
                v.z = fmaxf(0.f, v.z * sc.z + sh.z);
                v.w = fmaxf(0.f, v.w * sc.w + sh.w);
            }
            float* d = &sA[r * SAP + c4 * 4];
            d[0] = wmma::__float_to_tf32(v.x);
            d[1] = wmma::__float_to_tf32(v.y);
            d[2] = wmma::__float_to_tf32(v.z);
            d[3] = wmma::__float_to_tf32(v.w);
        }
        // ---- transform raw -> sB ----
#pragma unroll
        for (int p = 0; p < NPB; p++) {
            int idx = tid + p * 256;
            int r = idx / (BN / 4);
            int c4 = idx % (BN / 4);
            float4 v = ((const float4*)rawB)[idx];
            float* d = &sB[r * SBP + c4 * 4];
            d[0] = wmma::__float_to_tf32(v.x);
            d[1] = wmma::__float_to_tf32(v.y);
            d[2] = wmma::__float_to_tf32(v.z);
            d[3] = wmma::__float_to_tf32(v.w);
        }

        // ---- prefetch next tile; copy overlaps the mma below ----
        if (kt + BK < K) {
            issueA(kt + BK);
            issueB(kt + BK);
            CP_COMMIT();
        }
        __syncthreads();

        // ---- mma over current smem tile ----
#pragma unroll
        for (int kk = 0; kk < BK; kk += 8) {
            wmma::fragment<wmma::matrix_a, 16, 16, 8, wmma::precision::tf32,
                           wmma::row_major> af[MT];
            wmma::fragment<wmma::matrix_b, 16, 16, 8, wmma::precision::tf32,
                           wmma::row_major> bf[NT];
#pragma unroll
            for (int mt = 0; mt < MT; mt++)
                wmma::load_matrix_sync(af[mt],
                    &sA[(wm * WM + mt * 16) * SAP + kk], SAP);
#pragma unroll
            for (int nt = 0; nt < NT; nt++)
                wmma::load_matrix_sync(bf[nt],
                    &sB[kk * SBP + wn * WN + nt * 16], SBP);
#pragma unroll
            for (int mt = 0; mt < MT; mt++)
#pragma unroll
                for (int nt = 0; nt < NT; nt++)
                    wmma::mma_sync(acc[mt][nt], af[mt], bf[nt], acc[mt][nt]);
        }
    }

    float* C = g_H;
#pragma unroll
    for (int mt = 0; mt < MT; mt++) {
        int gr = row0 + wm * WM + mt * 16;
        if (gr >= M) continue;
#pragma unroll
        for (int nt = 0; nt < NT; nt++)
            wmma::store_matrix_sync(C + (size_t)gr * BN + wn * WN + nt * 16,
                                    acc[mt][nt], BN, wmma::mem_row_major);
    }
}

// dynamic smem sizes per instantiation
constexpr int GEMM_SMEM_BYTES(int BN) {
    return (128 * 40 + 32 * (BN + 8) + 128 * 32 + 32 * BN) * 4;
}

// ---------------- grid-stride aggregation + register-fused BN statistics ----
template <int D, bool STATS, bool EXT_OUT>
__global__ void __launch_bounds__(256)
k_agg(const float* __restrict__ bias, float* __restrict__ out_ext) {
    constexpr int VEC = D / 32;          // 4 (D=128) or 2 (D=64)
    __shared__ float bsum[STATS ? D : 1];
    __shared__ float bsq [STATS ? D : 1];

    const int tid = threadIdx.x;
    if (STATS) {
        if (tid < D) { bsum[tid] = 0.f; bsq[tid] = 0.f; }
        __syncthreads();
    }

    const int lane = tid & 31;
    const int base = lane * VEC;
    const int warpsPerBlock = 256 >> 5;  // 8
    int gw = blockIdx.x * warpsPerBlock + (tid >> 5);
    const int stride = gridDim.x * warpsPerBlock;
    const float* H = g_H;
    float* out = EXT_OUT ? out_ext : (float*)g_A;

    float bv[VEC];
#pragma unroll
    for (int q = 0; q < VEC; q++) bv[q] = bias[base + q];

    float sm[VEC], sq[VEC];
#pragma unroll
    for (int q = 0; q < VEC; q++) { sm[q] = 0.f; sq[q] = 0.f; }

    for (int node = gw; node < NNODES; node += stride) {
        float di = g_dinv[node];
        float self = di * di;

        if constexpr (VEC == 4) {
            float4 h = *(const float4*)(H + (size_t)node * D + base);
            float a0 = bv[0] + self * h.x;
            float a1 = bv[1] + self * h.y;
            float a2 = bv[2] + self * h.z;
            float a3 = bv[3] + self * h.w;
            float b0 = 0.f, b1 = 0.f, b2 = 0.f, b3 = 0.f;

            int j  = g_rowptr[node];
            int je = g_rowptr[node + 1];
            for (; j + 1 < je; j += 2) {
                int   s0 = __ldg(&g_col[j]),  s1 = __ldg(&g_col[j + 1]);
                float w0 = __ldg(&g_wgt[j]),  w1 = __ldg(&g_wgt[j + 1]);
                float4 x0 = *(const float4*)(H + (size_t)s0 * D + base);
                float4 x1 = *(const float4*)(H + (size_t)s1 * D + base);
                a0 += w0 * x0.x; a1 += w0 * x0.y; a2 += w0 * x0.z; a3 += w0 * x0.w;
                b0 += w1 * x1.x; b1 += w1 * x1.y; b2 += w1 * x1.z; b3 += w1 * x1.w;
            }
            if (j < je) {
                int   s0 = __ldg(&g_col[j]);
                float w0 = __ldg(&g_wgt[j]);
                float4 x0 = *(const float4*)(H + (size_t)s0 * D + base);
                a0 += w0 * x0.x; a1 += w0 * x0.y; a2 += w0 * x0.z; a3 += w0 * x0.w;
            }
            float v0 = a0 + b0, v1 = a1 + b1, v2 = a2 + b2, v3 = a3 + b3;
            *(float4*)(out + (size_t)node * D + base) = make_float4(v0, v1, v2, v3);
            if (STATS) {
                sm[0] += v0; sm[1] += v1; sm[2] += v2; sm[3] += v3;
                sq[0] += v0 * v0; sq[1] += v1 * v1;
                sq[2] += v2 * v2; sq[3] += v3 * v3;
            }
        } else {
            float2 h = *(const float2*)(H + (size_t)node * D + base);
            float a0 = bv[0] + self * h.x;
            float a1 = bv[1] + self * h.y;
            float b0 = 0.f, b1 = 0.f;

            int j  = g_rowptr[node];
            int je = g_rowptr[node + 1];
            for (; j + 1 < je; j += 2) {
                int   s0 = __ldg(&g_col[j]),  s1 = __ldg(&g_col[j + 1]);
                float w0 = __ldg(&g_wgt[j]),  w1 = __ldg(&g_wgt[j + 1]);
                float2 x0 = *(const float2*)(H + (size_t)s0 * D + base);
                float2 x1 = *(const float2*)(H + (size_t)s1 * D + base);
                a0 += w0 * x0.x; a1 += w0 * x0.y;
                b0 += w1 * x1.x; b1 += w1 * x1.y;
            }
            if (j < je) {
                int   s0 = __ldg(&g_col[j]);
                float w0 = __ldg(&g_wgt[j]);
                float2 x0 = *(const float2*)(H + (size_t)s0 * D + base);
                a0 += w0 * x0.x; a1 += w0 * x0.y;
            }
            float v0 = a0 + b0, v1 = a1 + b1;
            *(float2*)(out + (size_t)node * D + base) = make_float2(v0, v1);
            if (STATS) {
                sm[0] += v0; sm[1] += v1;
                sq[0] += v0 * v0; sq[1] += v1 * v1;
            }
        }
    }

    if (STATS) {
#pragma unroll
        for (int q = 0; q < VEC; q++) {
            atomicAdd(&bsum[base + q], sm[q]);
            atomicAdd(&bsq [base + q], sq[q]);
        }
        __syncthreads();
        if (tid < D) {
            atomicAdd(&g_stats[tid],     bsum[tid]);
            atomicAdd(&g_stats[D + tid], bsq[tid]);
        }
    }
}

// ---------------- BatchNorm finalize (also re-zeroes stats for next layer) ----
__global__ void k_bnfinal(const float* __restrict__ g, const float* __restrict__ bt) {
    int t = threadIdx.x;
    if (t >= DH) return;
    float invN = 1.0f / (float)NNODES;
    float mu = g_stats[t] * invN;
    float var = g_stats[DH + t] * invN - mu * mu;
    float r = rsqrtf(var + BN_EPS);
    float a = g[t] * r;
    g_scale[t] = a;
    g_shift[t] = bt[t] - mu * a;
    g_stats[t] = 0.f;
    g_stats[DH + t] = 0.f;
}

// ---------------- launcher ----------------
extern "C" void kernel_launch(void* const* d_in, const int* in_sizes, int n_in,
                              void* d_out, int out_size) {
    const float* x   = (const float*)d_in[0];
    const int*   ei  = (const int*)d_in[1];
    const float* W1  = (const float*)d_in[2];
    const float* b1  = (const float*)d_in[3];
    const float* g1  = (const float*)d_in[4];
    const float* bt1 = (const float*)d_in[5];
    const float* W2  = (const float*)d_in[6];
    const float* b2  = (const float*)d_in[7];
    const float* g2  = (const float*)d_in[8];
    const float* bt2 = (const float*)d_in[9];
    const float* W3  = (const float*)d_in[10];
    const float* b3  = (const float*)d_in[11];
    float* out = (float*)d_out;

    const int E = in_sizes[1] / 2;
    const int M = in_sizes[0] / DIN;

    constexpr int SM_H = GEMM_SMEM_BYTES(DH);    // 70656
    constexpr int SM_O = GEMM_SMEM_BYTES(DOUT);  // 54272
    cudaFuncSetAttribute(k_gemm_wmma<DH, false>,
                         cudaFuncAttributeMaxDynamicSharedMemorySize, SM_H);
    cudaFuncSetAttribute(k_gemm_wmma<DH, true>,
                         cudaFuncAttributeMaxDynamicSharedMemorySize, SM_H);
    cudaFuncSetAttribute(k_gemm_wmma<DOUT, true>,
                         cudaFuncAttributeMaxDynamicSharedMemorySize, SM_O);

    const int TB = 256;
    dim3 nodeGrid((NNODES + TB - 1) / TB);
    dim3 edgeGrid((E + TB - 1) / TB);
    dim3 gemmGrid((M + 127) / 128);

    // --- graph normalization + CSR build ---
    k_zero_node_ints<<<nodeGrid, TB>>>();
    k_count_deg<<<edgeGrid, TB>>>(ei, E);
    k_dinv<<<nodeGrid, TB>>>();
    k_scan1<<<NB_SCAN, 256>>>();
    k_scan2<<<1, 512>>>();
    k_scan3<<<NB_SCAN, 256>>>(E);
    k_scatter<<<edgeGrid, TB>>>(ei, E);

    // --- layer 1 ---
    k_gemm_wmma<DH, false><<<gemmGrid, 256, SM_H>>>(x, W1, M, DIN);
    k_agg<DH, true, false><<<AGG_BLOCKS, 256>>>(b1, nullptr);
    k_bnfinal<<<1, DH>>>(g1, bt1);

    // --- layer 2 (BN1+ReLU fused into GEMM A-load) ---
    k_gemm_wmma<DH, true><<<gemmGrid, 256, SM_H>>>(nullptr, W2, M, DH);
    k_agg<DH, true, false><<<AGG_BLOCKS, 256>>>(b2, nullptr);
    k_bnfinal<<<1, DH>>>(g2, bt2);

    // --- layer 3 (BN2+ReLU fused into GEMM A-load) ---
    k_gemm_wmma<DOUT, true><<<gemmGrid, 256, SM_O>>>(nullptr, W3, M, DH);
    k_agg<DOUT, false, true><<<AGG_BLOCKS, 256>>>(b3, out);
}

// round 15
// speedup vs baseline: 1.0640x; 1.0640x over previous
#include <cuda_runtime.h>
#include <mma.h>

using namespace nvcuda;

#define NNODES 100000
#define NEDGES 1600000
#define DIN 256
#define DH 128
#define DOUT 64
#define BN_EPS 1e-5f
#define NB_SCAN 391   // ceil(100000/256)
#define AGG_BLOCKS 1024

// ---------------- static device scratch ----------------
__device__ float g_dinv[NNODES];
__device__ int   g_deg[NNODES];
__device__ int   g_cursor[NNODES];
__device__ int   g_rowptr[NNODES + 1];
__device__ int   g_bsum[512];
__device__ int   g_col[NEDGES];
__device__ float g_wgt[NEDGES];
__device__ float g_H [NNODES * DH];   // GEMM output (XW)
__device__ float g_A [NNODES * DH];   // aggregated conv output (pre-BN)
__device__ float g_stats[2 * DH];     // column sums / sumsq
__device__ float g_scale[DH];
__device__ float g_shift[DH];

// ---------------- setup kernels ----------------
__global__ void k_zero_node_ints() {
    int i = blockIdx.x * blockDim.x + threadIdx.x;
    if (i < NNODES) { g_deg[i] = 0; g_cursor[i] = 0; }
    if (i < 2 * DH) g_stats[i] = 0.f;      // initial zero for layer-1 stats
}

__global__ void k_count_deg(const int* __restrict__ ei, int E) {
    int e = blockIdx.x * blockDim.x + threadIdx.x;
    if (e < E) atomicAdd(&g_deg[ei[E + e]], 1);
}

__global__ void k_dinv() {
    int i = blockIdx.x * blockDim.x + threadIdx.x;
    if (i < NNODES) g_dinv[i] = rsqrtf((float)(g_deg[i] + 1));
}

// ---- multi-block exclusive scan: deg -> rowptr ----
__global__ void k_scan1() {
    __shared__ int s[256];
    int t = threadIdx.x;
    int i = blockIdx.x * 256 + t;
    int v = (i < NNODES) ? g_deg[i] : 0;
    s[t] = v;
    __syncthreads();
#pragma unroll
    for (int off = 128; off > 0; off >>= 1) {
        if (t < off) s[t] += s[t + off];
        __syncthreads();
    }
    if (t == 0) g_bsum[blockIdx.x] = s[0];
}

__global__ void k_scan2() {
    __shared__ int s[512];
    int t = threadIdx.x;
    int v = (t < NB_SCAN) ? g_bsum[t] : 0;
    s[t] = v;
    __syncthreads();
    for (int off = 1; off < 512; off <<= 1) {
        int a = (t >= off) ? s[t - off] : 0;
        __syncthreads();
        s[t] += a;
        __syncthreads();
    }
    g_bsum[t] = s[t] - v;                 // exclusive
}

__global__ void k_scan3(int E) {
    __shared__ int s[256];
    int t = threadIdx.x;
    int i = blockIdx.x * 256 + t;
    int v = (i < NNODES) ? g_deg[i] : 0;
    s[t] = v;
    __syncthreads();
    for (int off = 1; off < 256; off <<= 1) {
        int a = (t >= off) ? s[t - off] : 0;
        __syncthreads();
        s[t] += a;
        __syncthreads();
    }
    if (i < NNODES) g_rowptr[i] = g_bsum[blockIdx.x] + s[t] - v;
    if (i == 0) g_rowptr[NNODES] = E;
}

__global__ void k_scatter(const int* __restrict__ ei, int E) {
    int e = blockIdx.x * blockDim.x + threadIdx.x;
    if (e >= E) return;
    int s = ei[e];
    int d = ei[E + e];
    int pos = g_rowptr[d] + atomicAdd(&g_cursor[d], 1);
    g_col[pos] = s;
    g_wgt[pos] = g_dinv[s] * g_dinv[d];
}

// ---------------- WMMA TF32 GEMM (round-6 verbatim) ----------------
// C(g_H)[M x BN] = op(A)[M x K] @ B[K x BN]
// FUSE=false: A = Aext;  FUSE=true: A = relu(g_A*scale[k]+shift[k])
template <int BN, bool FUSE>
__global__ void __launch_bounds__(256)
k_gemm_wmma(const float* __restrict__ Aext, const float* __restrict__ B, int M, int K) {
    constexpr int BM = 128, BK = 32;
    constexpr int SAP = 40;
    constexpr int SBP = BN + 8;
    constexpr int WROWS = 4, WCOLS = 2;
    constexpr int WM = BM / WROWS;       // 32
    constexpr int WN = BN / WCOLS;       // 64 or 32
    constexpr int MT = WM / 16;          // 2
    constexpr int NT = WN / 16;          // 4 or 2

    __shared__ __align__(16) float sA[BM * SAP];
    __shared__ __align__(16) float sB[BK * SBP];

    const float* A = FUSE ? (const float*)g_A : Aext;   // device-side select

    const int tid = threadIdx.x;
    const int wid = tid >> 5;
    const int wm = wid / WCOLS;
    const int wn = wid % WCOLS;
    const int row0 = blockIdx.x * BM;

    wmma::fragment<wmma::accumulator, 16, 16, 8, float> acc[MT][NT];
#pragma unroll
    for (int i = 0; i < MT; i++)
#pragma unroll
        for (int j = 0; j < NT; j++) wmma::fill_fragment(acc[i][j], 0.0f);

    constexpr int NPB = (BK * BN / 4) / 256;

    for (int kt = 0; kt < K; kt += BK) {
#pragma unroll
        for (int p = 0; p < 4; p++) {
            int idx = tid + p * 256;
            int r = idx >> 3;
            int c4 = idx & 7;
            int gr = row0 + r;
            float4 v = make_float4(0.f, 0.f, 0.f, 0.f);
            if (gr < M) v = *(const float4*)(A + (size_t)gr * K + kt + c4 * 4);
            if (FUSE) {
                float4 sc = *(const float4*)(g_scale + kt + c4 * 4);
                float4 sh = *(const float4*)(g_shift + kt + c4 * 4);
                v.x = fmaxf(0.f, v.x * sc.x + sh.x);
                v.y = fmaxf(0.f, v.y * sc.y + sh.y);
                v.z = fmaxf(0.f, v.z * sc.z + sh.z);
                v.w = fmaxf(0.f, v.w * sc.w + sh.w);
            }
            float* d = &sA[r * SAP + c4 * 4];
            d[0] = wmma::__float_to_tf32(v.x);
            d[1] = wmma::__float_to_tf32(v.y);
            d[2] = wmma::__float_to_tf32(v.z);
            d[3] = wmma::__float_to_tf32(v.w);
        }
#pragma unroll
        for (int p = 0; p < NPB; p++) {
            int idx = tid + p * 256;
            int r = idx / (BN / 4);
            int c4 = idx % (BN / 4);
            float4 v = *(const float4*)(B + (size_t)(kt + r) * BN + c4 * 4);
            float* d = &sB[r * SBP + c4 * 4];
            d[0] = wmma::__float_to_tf32(v.x);
            d[1] = wmma::__float_to_tf32(v.y);
            d[2] = wmma::__float_to_tf32(v.z);
            d[3] = wmma::__float_to_tf32(v.w);
        }
        __syncthreads();

#pragma unroll
        for (int kk = 0; kk < BK; kk += 8) {
            wmma::fragment<wmma::matrix_a, 16, 16, 8, wmma::precision::tf32,
                           wmma::row_major> af[MT];
            wmma::fragment<wmma::matrix_b, 16, 16, 8, wmma::precision::tf32,
                           wmma::row_major> bf[NT];
#pragma unroll
            for (int mt = 0; mt < MT; mt++)
                wmma::load_matrix_sync(af[mt],
                    &sA[(wm * WM + mt * 16) * SAP + kk], SAP);
#pragma unroll
            for (int nt = 0; nt < NT; nt++)
                wmma::load_matrix_sync(bf[nt],
                    &sB[kk * SBP + wn * WN + nt * 16], SBP);
#pragma unroll
            for (int mt = 0; mt < MT; mt++)
#pragma unroll
                for (int nt = 0; nt < NT; nt++)
                    wmma::mma_sync(acc[mt][nt], af[mt], bf[nt], acc[mt][nt]);
        }
        __syncthreads();
    }

    float* C = g_H;
#pragma unroll
    for (int mt = 0; mt < MT; mt++) {
        int gr = row0 + wm * WM + mt * 16;
        if (gr >= M) continue;
#pragma unroll
        for (int nt = 0; nt < NT; nt++)
            wmma::store_matrix_sync(C + (size_t)gr * BN + wn * WN + nt * 16,
                                    acc[mt][nt], BN, wmma::mem_row_major);
    }
}

// ---------------- grid-stride aggregation + register-fused BN statistics ----
template <int D, bool STATS, bool EXT_OUT>
__global__ void __launch_bounds__(256)
k_agg(const float* __restrict__ bias, float* __restrict__ out_ext) {
    constexpr int VEC = D / 32;          // 4 (D=128) or 2 (D=64)
    __shared__ float bsum[STATS ? D : 1];
    __shared__ float bsq [STATS ? D : 1];

    const int tid = threadIdx.x;
    if (STATS) {
        if (tid < D) { bsum[tid] = 0.f; bsq[tid] = 0.f; }
        __syncthreads();
    }

    const int lane = tid & 31;
    const int base = lane * VEC;
    const int warpsPerBlock = 256 >> 5;  // 8
    int gw = blockIdx.x * warpsPerBlock + (tid >> 5);
    const int stride = gridDim.x * warpsPerBlock;
    const float* H = g_H;
    float* out = EXT_OUT ? out_ext : (float*)g_A;

    float bv[VEC];
#pragma unroll
    for (int q = 0; q < VEC; q++) bv[q] = bias[base + q];

    float sm[VEC], sq[VEC];
#pragma unroll
    for (int q = 0; q < VEC; q++) { sm[q] = 0.f; sq[q] = 0.f; }

    for (int node = gw; node < NNODES; node += stride) {
        float di = g_dinv[node];
        float self = di * di;

        if constexpr (VEC == 4) {
            float4 h = *(const float4*)(H + (size_t)node * D + base);
            float a0 = bv[0] + self * h.x;
            float a1 = bv[1] + self * h.y;
            float a2 = bv[2] + self * h.z;
            float a3 = bv[3] + self * h.w;
            float b0 = 0.f, b1 = 0.f, b2 = 0.f, b3 = 0.f;

            int j  = g_rowptr[node];
            int je = g_rowptr[node + 1];
            for (; j + 1 < je; j += 2) {
                int   s0 = __ldg(&g_col[j]),  s1 = __ldg(&g_col[j + 1]);
                float w0 = __ldg(&g_wgt[j]),  w1 = __ldg(&g_wgt[j + 1]);
                float4 x0 = *(const float4*)(H + (size_t)s0 * D + base);
                float4 x1 = *(const float4*)(H + (size_t)s1 * D + base);
                a0 += w0 * x0.x; a1 += w0 * x0.y; a2 += w0 * x0.z; a3 += w0 * x0.w;
                b0 += w1 * x1.x; b1 += w1 * x1.y; b2 += w1 * x1.z; b3 += w1 * x1.w;
            }
            if (j < je) {
                int   s0 = __ldg(&g_col[j]);
                float w0 = __ldg(&g_wgt[j]);
                float4 x0 = *(const float4*)(H + (size_t)s0 * D + base);
                a0 += w0 * x0.x; a1 += w0 * x0.y; a2 += w0 * x0.z; a3 += w0 * x0.w;
            }
            float v0 = a0 + b0, v1 = a1 + b1, v2 = a2 + b2, v3 = a3 + b3;
            *(float4*)(out + (size_t)node * D + base) = make_float4(v0, v1, v2, v3);
            if (STATS) {
                sm[0] += v0; sm[1] += v1; sm[2] += v2; sm[3] += v3;
                sq[0] += v0 * v0; sq[1] += v1 * v1;
                sq[2] += v2 * v2; sq[3] += v3 * v3;
            }
        } else {
            float2 h = *(const float2*)(H + (size_t)node * D + base);
            float a0 = bv[0] + self * h.x;
            float a1 = bv[1] + self * h.y;
            float b0 = 0.f, b1 = 0.f;

            int j  = g_rowptr[node];
            int je = g_rowptr[node + 1];
            for (; j + 1 < je; j += 2) {
                int   s0 = __ldg(&g_col[j]),  s1 = __ldg(&g_col[j + 1]);
                float w0 = __ldg(&g_wgt[j]),  w1 = __ldg(&g_wgt[j + 1]);
                float2 x0 = *(const float2*)(H + (size_t)s0 * D + base);
                float2 x1 = *(const float2*)(H + (size_t)s1 * D + base);
                a0 += w0 * x0.x; a1 += w0 * x0.y;
                b0 += w1 * x1.x; b1 += w1 * x1.y;
            }
            if (j < je) {
                int   s0 = __ldg(&g_col[j]);
                float w0 = __ldg(&g_wgt[j]);
                float2 x0 = *(const float2*)(H + (size_t)s0 * D + base);
                a0 += w0 * x0.x; a1 += w0 * x0.y;
            }
            float v0 = a0 + b0, v1 = a1 + b1;
            *(float2*)(out + (size_t)node * D + base) = make_float2(v0, v1);
            if (STATS) {
                sm[0] += v0; sm[1] += v1;
                sq[0] += v0 * v0; sq[1] += v1 * v1;
            }
        }
    }

    if (STATS) {
#pragma unroll
        for (int q = 0; q < VEC; q++) {
            atomicAdd(&bsum[base + q], sm[q]);
            atomicAdd(&bsq [base + q], sq[q]);
        }
        __syncthreads();
        if (tid < D) {
            atomicAdd(&g_stats[tid],     bsum[tid]);
            atomicAdd(&g_stats[D + tid], bsq[tid]);
        }
    }
}

// ---------------- BatchNorm finalize (also re-zeroes stats for next layer) ----
__global__ void k_bnfinal(const float* __restrict__ g, const float* __restrict__ bt) {
    int t = threadIdx.x;
    if (t >= DH) return;
    float invN = 1.0f / (float)NNODES;
    float mu = g_stats[t] * invN;
    float var = g_stats[DH + t] * invN - mu * mu;
    float r = rsqrtf(var + BN_EPS);
    float a = g[t] * r;
    g_scale[t] = a;
    g_shift[t] = bt[t] - mu * a;
    g_stats[t] = 0.f;
    g_stats[DH + t] = 0.f;
}

// ---------------- launcher ----------------
extern "C" void kernel_launch(void* const* d_in, const int* in_sizes, int n_in,
                              void* d_out, int out_size) {
    const float* x   = (const float*)d_in[0];
    const int*   ei  = (const int*)d_in[1];
    const float* W1  = (const float*)d_in[2];
    const float* b1  = (const float*)d_in[3];
    const float* g1  = (const float*)d_in[4];
    const float* bt1 = (const float*)d_in[5];
    const float* W2  = (const float*)d_in[6];
    const float* b2  = (const float*)d_in[7];
    const float* g2  = (const float*)d_in[8];
    const float* bt2 = (const float*)d_in[9];
    const float* W3  = (const float*)d_in[10];
    const float* b3  = (const float*)d_in[11];
    float* out = (float*)d_out;

    const int E = in_sizes[1] / 2;
    const int M = in_sizes[0] / DIN;

    const int TB = 256;
    dim3 nodeGrid((NNODES + TB - 1) / TB);
    dim3 edgeGrid((E + TB - 1) / TB);
    dim3 gemmGrid((M + 127) / 128);

    // fork/join resources (host-side; created per call, leaked — kernel_launch
    // runs only a handful of times; graph replays re-run GPU work only)
    cudaStream_t s2;
    cudaStreamCreateWithFlags(&s2, cudaStreamNonBlocking);
    cudaEvent_t e0, e1;
    cudaEventCreateWithFlags(&e0, cudaEventDisableTiming);
    cudaEventCreateWithFlags(&e1, cudaEventDisableTiming);

    // ---- fork: GEMM1 (depends only on x/W1) runs on s2, CSR build on default ----
    cudaEventRecord(e0, 0);
    cudaStreamWaitEvent(s2, e0, 0);
    k_gemm_wmma<DH, false><<<gemmGrid, 256, 0, s2>>>(x, W1, M, DIN);
    cudaEventRecord(e1, s2);

    // --- graph normalization + CSR build (default stream, overlaps GEMM1) ---
    k_zero_node_ints<<<nodeGrid, TB>>>();
    k_count_deg<<<edgeGrid, TB>>>(ei, E);
    k_dinv<<<nodeGrid, TB>>>();
    k_scan1<<<NB_SCAN, 256>>>();
    k_scan2<<<1, 512>>>();
    k_scan3<<<NB_SCAN, 256>>>(E);
    k_scatter<<<edgeGrid, TB>>>(ei, E);

    // ---- join: layer-1 agg needs both CSR and GEMM1 ----
    cudaStreamWaitEvent(0, e1, 0);

    // --- layer 1 ---
    k_agg<DH, true, false><<<AGG_BLOCKS, 256>>>(b1, nullptr);
    k_bnfinal<<<1, DH>>>(g1, bt1);

    // --- layer 2 (BN1+ReLU fused into GEMM A-load) ---
    k_gemm_wmma<DH, true><<<gemmGrid, 256>>>(nullptr, W2, M, DH);
    k_agg<DH, true, false><<<AGG_BLOCKS, 256>>>(b2, nullptr);
    k_bnfinal<<<1, DH>>>(g2, bt2);

    // --- layer 3 (BN2+ReLU fused into GEMM A-load) ---
    k_gemm_wmma<DOUT, true><<<gemmGrid, 256>>>(nullptr, W3, M, DH);
    k_agg<DOUT, false, true><<<AGG_BLOCKS, 256>>>(b3, out);
}

// round 16
// speedup vs baseline: 1.1392x; 1.0707x over previous
#include <cuda_runtime.h>
#include <cuda_fp16.h>
#include <cstdint>
#include <mma.h>

using namespace nvcuda;

#define NNODES 100000
#define NEDGES 1600000
#define DIN 256
#define DH 128
#define DOUT 64
#define BN_EPS 1e-5f
#define NB_SCAN 391   // ceil(100000/256)
#define AGG_BLOCKS 1024

// ---------------- static device scratch ----------------
__device__ float  g_dinv[NNODES];
__device__ int    g_deg[NNODES];
__device__ int    g_cursor[NNODES];
__device__ int    g_rowptr[NNODES + 1];
__device__ int    g_bsum[512];
__device__ int    g_col[NEDGES];
__device__ float  g_wgt[NEDGES];
__device__ __half g_H [NNODES * DH];   // GEMM output (XW) in fp16 (gather operand)
__device__ float  g_A [NNODES * DH];   // aggregated conv output (pre-BN, fp32)
__device__ float  g_stats[2 * DH];     // column sums / sumsq
__device__ float  g_scale[DH];
__device__ float  g_shift[DH];

// ---------------- setup kernels ----------------
__global__ void k_zero_node_ints() {
    int i = blockIdx.x * blockDim.x + threadIdx.x;
    if (i < NNODES) { g_deg[i] = 0; g_cursor[i] = 0; }
    if (i < 2 * DH) g_stats[i] = 0.f;      // initial zero for layer-1 stats
}

__global__ void k_count_deg(const int* __restrict__ ei, int E) {
    int e = blockIdx.x * blockDim.x + threadIdx.x;
    if (e < E) atomicAdd(&g_deg[ei[E + e]], 1);
}

__global__ void k_dinv() {
    int i = blockIdx.x * blockDim.x + threadIdx.x;
    if (i < NNODES) g_dinv[i] = rsqrtf((float)(g_deg[i] + 1));
}

// ---- multi-block exclusive scan: deg -> rowptr ----
__global__ void k_scan1() {
    __shared__ int s[256];
    int t = threadIdx.x;
    int i = blockIdx.x * 256 + t;
    int v = (i < NNODES) ? g_deg[i] : 0;
    s[t] = v;
    __syncthreads();
#pragma unroll
    for (int off = 128; off > 0; off >>= 1) {
        if (t < off) s[t] += s[t + off];
        __syncthreads();
    }
    if (t == 0) g_bsum[blockIdx.x] = s[0];
}

__global__ void k_scan2() {
    __shared__ int s[512];
    int t = threadIdx.x;
    int v = (t < NB_SCAN) ? g_bsum[t] : 0;
    s[t] = v;
    __syncthreads();
    for (int off = 1; off < 512; off <<= 1) {
        int a = (t >= off) ? s[t - off] : 0;
        __syncthreads();
        s[t] += a;
        __syncthreads();
    }
    g_bsum[t] = s[t] - v;                 // exclusive
}

__global__ void k_scan3(int E) {
    __shared__ int s[256];
    int t = threadIdx.x;
    int i = blockIdx.x * 256 + t;
    int v = (i < NNODES) ? g_deg[i] : 0;
    s[t] = v;
    __syncthreads();
    for (int off = 1; off < 256; off <<= 1) {
        int a = (t >= off) ? s[t - off] : 0;
        __syncthreads();
        s[t] += a;
        __syncthreads();
    }
    if (i < NNODES) g_rowptr[i] = g_bsum[blockIdx.x] + s[t] - v;
    if (i == 0) g_rowptr[NNODES] = E;
}

__global__ void k_scatter(const int* __restrict__ ei, int E) {
    int e = blockIdx.x * blockDim.x + threadIdx.x;
    if (e >= E) return;
    int s = ei[e];
    int d = ei[E + e];
    int pos = g_rowptr[d] + atomicAdd(&g_cursor[d], 1);
    g_col[pos] = s;
    g_wgt[pos] = g_dinv[s] * g_dinv[d];
}

// ---------------- WMMA TF32 GEMM (round-6 core, fp16 epilogue) ----------------
// g_H[M x BN] (fp16) = op(A)[M x K] @ B[K x BN]
// FUSE=false: A = Aext;  FUSE=true: A = relu(g_A*scale[k]+shift[k])
template <int BN, bool FUSE>
__global__ void __launch_bounds__(256)
k_gemm_wmma(const float* __restrict__ Aext, const float* __restrict__ B, int M, int K) {
    constexpr int BM = 128, BK = 32;
    constexpr int SAP = 40;
    constexpr int SBP = BN + 8;
    constexpr int WROWS = 4, WCOLS = 2;
    constexpr int WM = BM / WROWS;       // 32
    constexpr int WN = BN / WCOLS;       // 64 or 32
    constexpr int MT = WM / 16;          // 2
    constexpr int NT = WN / 16;          // 4 or 2
    constexpr int STG_LD = 24;           // staging ldm (mult of 4)

    __shared__ __align__(16) float sA[BM * SAP];
    __shared__ __align__(16) float sB[BK * SBP];

    const float* A = FUSE ? (const float*)g_A : Aext;   // device-side select

    const int tid = threadIdx.x;
    const int wid = tid >> 5;
    const int lane = tid & 31;
    const int wm = wid / WCOLS;
    const int wn = wid % WCOLS;
    const int row0 = blockIdx.x * BM;

    wmma::fragment<wmma::accumulator, 16, 16, 8, float> acc[MT][NT];
#pragma unroll
    for (int i = 0; i < MT; i++)
#pragma unroll
        for (int j = 0; j < NT; j++) wmma::fill_fragment(acc[i][j], 0.0f);

    constexpr int NPB = (BK * BN / 4) / 256;

    for (int kt = 0; kt < K; kt += BK) {
#pragma unroll
        for (int p = 0; p < 4; p++) {
            int idx = tid + p * 256;
            int r = idx >> 3;
            int c4 = idx & 7;
            int gr = row0 + r;
            float4 v = make_float4(0.f, 0.f, 0.f, 0.f);
            if (gr < M) v = *(const float4*)(A + (size_t)gr * K + kt + c4 * 4);
            if (FUSE) {
                float4 sc = *(const float4*)(g_scale + kt + c4 * 4);
                float4 sh = *(const float4*)(g_shift + kt + c4 * 4);
                v.x = fmaxf(0.f, v.x * sc.x + sh.x);
                v.y = fmaxf(0.f, v.y * sc.y + sh.y);
                v.z = fmaxf(0.f, v.z * sc.z + sh.z);
                v.w = fmaxf(0.f, v.w * sc.w + sh.w);
            }
            float* d = &sA[r * SAP + c4 * 4];
            d[0] = wmma::__float_to_tf32(v.x);
            d[1] = wmma::__float_to_tf32(v.y);
            d[2] = wmma::__float_to_tf32(v.z);
            d[3] = wmma::__float_to_tf32(v.w);
        }
#pragma unroll
        for (int p = 0; p < NPB; p++) {
            int idx = tid + p * 256;
            int r = idx / (BN / 4);
            int c4 = idx % (BN / 4);
            float4 v = *(const float4*)(B + (size_t)(kt + r) * BN + c4 * 4);
            float* d = &sB[r * SBP + c4 * 4];
            d[0] = wmma::__float_to_tf32(v.x);
            d[1] = wmma::__float_to_tf32(v.y);
            d[2] = wmma::__float_to_tf32(v.z);
            d[3] = wmma::__float_to_tf32(v.w);
        }
        __syncthreads();

#pragma unroll
        for (int kk = 0; kk < BK; kk += 8) {
            wmma::fragment<wmma::matrix_a, 16, 16, 8, wmma::precision::tf32,
                           wmma::row_major> af[MT];
            wmma::fragment<wmma::matrix_b, 16, 16, 8, wmma::precision::tf32,
                           wmma::row_major> bf[NT];
#pragma unroll
            for (int mt = 0; mt < MT; mt++)
                wmma::load_matrix_sync(af[mt],
                    &sA[(wm * WM + mt * 16) * SAP + kk], SAP);
#pragma unroll
            for (int nt = 0; nt < NT; nt++)
                wmma::load_matrix_sync(bf[nt],
                    &sB[kk * SBP + wn * WN + nt * 16], SBP);
#pragma unroll
            for (int mt = 0; mt < MT; mt++)
#pragma unroll
                for (int nt = 0; nt < NT; nt++)
                    wmma::mma_sync(acc[mt][nt], af[mt], bf[nt], acc[mt][nt]);
        }
        __syncthreads();
    }

    // ---- epilogue: fragments -> smem staging -> fp16 global ----
    // reuse sA as per-warp staging (8 warps x 16x24 floats = 3072 <= 5120)
    float* stage = &sA[wid * (16 * STG_LD)];
    const int r  = lane >> 1;            // 0..15
    const int c0 = (lane & 1) * 8;       // 0 or 8
#pragma unroll
    for (int mt = 0; mt < MT; mt++) {
#pragma unroll
        for (int nt = 0; nt < NT; nt++) {
            wmma::store_matrix_sync(stage, acc[mt][nt], STG_LD, wmma::mem_row_major);
            __syncwarp();
            int gr = row0 + wm * WM + mt * 16 + r;
            if (gr < M) {
                int gc = wn * WN + nt * 16 + c0;
                __half hbuf[8];
#pragma unroll
                for (int q = 0; q < 8; q++)
                    hbuf[q] = __float2half(stage[r * STG_LD + c0 + q]);
                *(uint4*)(g_H + (size_t)gr * BN + gc) = *(uint4*)hbuf;
            }
            __syncwarp();
        }
    }
}

// ---------------- grid-stride aggregation + register-fused BN statistics ----
// 1 warp per node; H gathered in fp16 (half the gather bytes), fp32 accumulate.
template <int D, bool STATS, bool EXT_OUT>
__global__ void __launch_bounds__(256)
k_agg(const float* __restrict__ bias, float* __restrict__ out_ext) {
    constexpr int VEC = D / 32;          // 4 (D=128) or 2 (D=64)
    __shared__ float bsum[STATS ? D : 1];
    __shared__ float bsq [STATS ? D : 1];

    const int tid = threadIdx.x;
    if (STATS) {
        if (tid < D) { bsum[tid] = 0.f; bsq[tid] = 0.f; }
        __syncthreads();
    }

    const int lane = tid & 31;
    const int base = lane * VEC;
    const int warpsPerBlock = 256 >> 5;  // 8
    int gw = blockIdx.x * warpsPerBlock + (tid >> 5);
    const int stride = gridDim.x * warpsPerBlock;
    const __half* H = g_H;
    float* out = EXT_OUT ? out_ext : (float*)g_A;

    float bv[VEC];
#pragma unroll
    for (int q = 0; q < VEC; q++) bv[q] = bias[base + q];

    float sm[VEC], sq[VEC];
#pragma unroll
    for (int q = 0; q < VEC; q++) { sm[q] = 0.f; sq[q] = 0.f; }

    for (int node = gw; node < NNODES; node += stride) {
        float di = g_dinv[node];
        float self = di * di;

        if constexpr (VEC == 4) {
            uint2 hr = *(const uint2*)(H + (size_t)node * D + base);
            float2 ha = __half22float2(*(__half2*)&hr.x);
            float2 hb = __half22float2(*(__half2*)&hr.y);
            float a0 = bv[0] + self * ha.x;
            float a1 = bv[1] + self * ha.y;
            float a2 = bv[2] + self * hb.x;
            float a3 = bv[3] + self * hb.y;
            float b0 = 0.f, b1 = 0.f, b2 = 0.f, b3 = 0.f;

            int j  = g_rowptr[node];
            int je = g_rowptr[node + 1];
            for (; j + 1 < je; j += 2) {
                int   s0 = __ldg(&g_col[j]),  s1 = __ldg(&g_col[j + 1]);
                float w0 = __ldg(&g_wgt[j]),  w1 = __ldg(&g_wgt[j + 1]);
                uint2 r0 = *(const uint2*)(H + (size_t)s0 * D + base);
                uint2 r1 = *(const uint2*)(H + (size_t)s1 * D + base);
                float2 x0a = __half22float2(*(__half2*)&r0.x);
                float2 x0b = __half22float2(*(__half2*)&r0.y);
                float2 x1a = __half22float2(*(__half2*)&r1.x);
                float2 x1b = __half22float2(*(__half2*)&r1.y);
                a0 += w0 * x0a.x; a1 += w0 * x0a.y; a2 += w0 * x0b.x; a3 += w0 * x0b.y;
                b0 += w1 * x1a.x; b1 += w1 * x1a.y; b2 += w1 * x1b.x; b3 += w1 * x1b.y;
            }
            if (j < je) {
                int   s0 = __ldg(&g_col[j]);
                float w0 = __ldg(&g_wgt[j]);
                uint2 r0 = *(const uint2*)(H + (size_t)s0 * D + base);
                float2 x0a = __half22float2(*(__half2*)&r0.x);
                float2 x0b = __half22float2(*(__half2*)&r0.y);
                a0 += w0 * x0a.x; a1 += w0 * x0a.y; a2 += w0 * x0b.x; a3 += w0 * x0b.y;
            }
            float v0 = a0 + b0, v1 = a1 + b1, v2 = a2 + b2, v3 = a3 + b3;
            *(float4*)(out + (size_t)node * D + base) = make_float4(v0, v1, v2, v3);
            if (STATS) {
                sm[0] += v0; sm[1] += v1; sm[2] += v2; sm[3] += v3;
                sq[0] += v0 * v0; sq[1] += v1 * v1;
                sq[2] += v2 * v2; sq[3] += v3 * v3;
            }
        } else {
            uint32_t hr = *(const uint32_t*)(H + (size_t)node * D + base);
            float2 ha = __half22float2(*(__half2*)&hr);
            float a0 = bv[0] + self * ha.x;
            float a1 = bv[1] + self * ha.y;
            float b0 = 0.f, b1 = 0.f;

            int j  = g_rowptr[node];
            int je = g_rowptr[node + 1];
            for (; j + 1 < je; j += 2) {
                int   s0 = __ldg(&g_col[j]),  s1 = __ldg(&g_col[j + 1]);
                float w0 = __ldg(&g_wgt[j]),  w1 = __ldg(&g_wgt[j + 1]);
                uint32_t r0 = *(const uint32_t*)(H + (size_t)s0 * D + base);
                uint32_t r1 = *(const uint32_t*)(H + (size_t)s1 * D + base);
                float2 x0 = __half22float2(*(__half2*)&r0);
                float2 x1 = __half22float2(*(__half2*)&r1);
                a0 += w0 * x0.x; a1 += w0 * x0.y;
                b0 += w1 * x1.x; b1 += w1 * x1.y;
            }
            if (j < je) {
                int   s0 = __ldg(&g_col[j]);
                float w0 = __ldg(&g_wgt[j]);
                uint32_t r0 = *(const uint32_t*)(H + (size_t)s0 * D + base);
                float2 x0 = __half22float2(*(__half2*)&r0);
                a0 += w0 * x0.x; a1 += w0 * x0.y;
            }
            float v0 = a0 + b0, v1 = a1 + b1;
            *(float2*)(out + (size_t)node * D + base) = make_float2(v0, v1);
            if (STATS) {
                sm[0] += v0; sm[1] += v1;
                sq[0] += v0 * v0; sq[1] += v1 * v1;
            }
        }
    }

    if (STATS) {
#pragma unroll
        for (int q = 0; q < VEC; q++) {
            atomicAdd(&bsum[base + q], sm[q]);
            atomicAdd(&bsq [base + q], sq[q]);
        }
        __syncthreads();
        if (tid < D) {
            atomicAdd(&g_stats[tid],     bsum[tid]);
            atomicAdd(&g_stats[D + tid], bsq[tid]);
        }
    }
}

// ---------------- BatchNorm finalize (also re-zeroes stats for next layer) ----
__global__ void k_bnfinal(const float* __restrict__ g, const float* __restrict__ bt) {
    int t = threadIdx.x;
    if (t >= DH) return;
    float invN = 1.0f / (float)NNODES;
    float mu = g_stats[t] * invN;
    float var = g_stats[DH + t] * invN - mu * mu;
    float r = rsqrtf(var + BN_EPS);
    float a = g[t] * r;
    g_scale[t] = a;
    g_shift[t] = bt[t] - mu * a;
    g_stats[t] = 0.f;
    g_stats[DH + t] = 0.f;
}

// ---------------- launcher ----------------
extern "C" void kernel_launch(void* const* d_in, const int* in_sizes, int n_in,
                              void* d_out, int out_size) {
    const float* x   = (const float*)d_in[0];
    const int*   ei  = (const int*)d_in[1];
    const float* W1  = (const float*)d_in[2];
    const float* b1  = (const float*)d_in[3];
    const float* g1  = (const float*)d_in[4];
    const float* bt1 = (const float*)d_in[5];
    const float* W2  = (const float*)d_in[6];
    const float* b2  = (const float*)d_in[7];
    const float* g2  = (const float*)d_in[8];
    const float* bt2 = (const float*)d_in[9];
    const float* W3  = (const float*)d_in[10];
    const float* b3  = (const float*)d_in[11];
    float* out = (float*)d_out;

    const int E = in_sizes[1] / 2;
    const int M = in_sizes[0] / DIN;

    const int TB = 256;
    dim3 nodeGrid((NNODES + TB - 1) / TB);
    dim3 edgeGrid((E + TB - 1) / TB);
    dim3 gemmGrid((M + 127) / 128);

    // fork/join resources (host-side; created per call, leaked — kernel_launch
    // runs only a handful of times; graph replays re-run GPU work only)
    cudaStream_t s2;
    cudaStreamCreateWithFlags(&s2, cudaStreamNonBlocking);
    cudaEvent_t e0, e1;
    cudaEventCreateWithFlags(&e0, cudaEventDisableTiming);
    cudaEventCreateWithFlags(&e1, cudaEventDisableTiming);

    // ---- fork: GEMM1 (depends only on x/W1) runs on s2, CSR build on default ----
    cudaEventRecord(e0, 0);
    cudaStreamWaitEvent(s2, e0, 0);
    k_gemm_wmma<DH, false><<<gemmGrid, 256, 0, s2>>>(x, W1, M, DIN);
    cudaEventRecord(e1, s2);

    // --- graph normalization + CSR build (default stream, overlaps GEMM1) ---
    k_zero_node_ints<<<nodeGrid, TB>>>();
    k_count_deg<<<edgeGrid, TB>>>(ei, E);
    k_dinv<<<nodeGrid, TB>>>();
    k_scan1<<<NB_SCAN, 256>>>();
    k_scan2<<<1, 512>>>();
    k_scan3<<<NB_SCAN, 256>>>(E);
    k_scatter<<<edgeGrid, TB>>>(ei, E);

    // ---- join: layer-1 agg needs both CSR and GEMM1 ----
    cudaStreamWaitEvent(0, e1, 0);

    // --- layer 1 ---
    k_agg<DH, true, false><<<AGG_BLOCKS, 256>>>(b1, nullptr);
    k_bnfinal<<<1, DH>>>(g1, bt1);

    // --- layer 2 (BN1+ReLU fused into GEMM A-load) ---
    k_gemm_wmma<DH, true><<<gemmGrid, 256>>>(nullptr, W2, M, DH);
    k_agg<DH, true, false><<<AGG_BLOCKS, 256>>>(b2, nullptr);
    k_bnfinal<<<1, DH>>>(g2, bt2);

    // --- layer 3 (BN2+ReLU fused into GEMM A-load) ---
    k_gemm_wmma<DOUT, true><<<gemmGrid, 256>>>(nullptr, W3, M, DH);
    k_agg<DOUT, false, true><<<AGG_BLOCKS, 256>>>(b3, out);
}

// round 17
// speedup vs baseline: 1.4769x; 1.2964x over previous
#include <cuda_runtime.h>
#include <cuda_fp16.h>
#include <cstdint>
#include <mma.h>

using namespace nvcuda;

#define NNODES 100000
#define NEDGES 1600000
#define DIN 256
#define DH 128
#define DOUT 64
#define BN_EPS 1e-5f
#define NB_SCAN 391   // ceil(100000/256)
#define AGG_BLOCKS 1024

// ---------------- static device scratch ----------------
__device__ float  g_dinv[NNODES];
__device__ int    g_deg[NNODES];
__device__ int    g_cursor[NNODES];
__device__ int    g_rowptr[NNODES + 1];
__device__ int    g_bsum[512];
__device__ int    g_col[NEDGES];
__device__ float  g_wgt[NEDGES];
__device__ __half g_H [NNODES * DH];   // GEMM output (XW) in fp16 (gather operand)
__device__ float  g_A [NNODES * DH];   // aggregated conv output (pre-BN, fp32)
__device__ float  g_stats[2 * DH];     // column sums / sumsq
__device__ float  g_scale[DH];
__device__ float  g_shift[DH];

// ---------------- setup kernels ----------------
__global__ void k_zero_node_ints() {
    int i = blockIdx.x * blockDim.x + threadIdx.x;
    if (i < NNODES) { g_deg[i] = 0; g_cursor[i] = 0; }
    if (i < 2 * DH) g_stats[i] = 0.f;      // initial zero for layer-1 stats
}

__global__ void k_count_deg(const int* __restrict__ ei, int E) {
    int e = blockIdx.x * blockDim.x + threadIdx.x;
    if (e < E) atomicAdd(&g_deg[ei[E + e]], 1);
}

__global__ void k_dinv() {
    int i = blockIdx.x * blockDim.x + threadIdx.x;
    if (i < NNODES) g_dinv[i] = rsqrtf((float)(g_deg[i] + 1));
}

// ---- multi-block exclusive scan: deg -> rowptr ----
__global__ void k_scan1() {
    __shared__ int s[256];
    int t = threadIdx.x;
    int i = blockIdx.x * 256 + t;
    int v = (i < NNODES) ? g_deg[i] : 0;
    s[t] = v;
    __syncthreads();
#pragma unroll
    for (int off = 128; off > 0; off >>= 1) {
        if (t < off) s[t] += s[t + off];
        __syncthreads();
    }
    if (t == 0) g_bsum[blockIdx.x] = s[0];
}

__global__ void k_scan2() {
    __shared__ int s[512];
    int t = threadIdx.x;
    int v = (t < NB_SCAN) ? g_bsum[t] : 0;
    s[t] = v;
    __syncthreads();
    for (int off = 1; off < 512; off <<= 1) {
        int a = (t >= off) ? s[t - off] : 0;
        __syncthreads();
        s[t] += a;
        __syncthreads();
    }
    g_bsum[t] = s[t] - v;                 // exclusive
}

__global__ void k_scan3(int E) {
    __shared__ int s[256];
    int t = threadIdx.x;
    int i = blockIdx.x * 256 + t;
    int v = (i < NNODES) ? g_deg[i] : 0;
    s[t] = v;
    __syncthreads();
    for (int off = 1; off < 256; off <<= 1) {
        int a = (t >= off) ? s[t - off] : 0;
        __syncthreads();
        s[t] += a;
        __syncthreads();
    }
    if (i < NNODES) g_rowptr[i] = g_bsum[blockIdx.x] + s[t] - v;
    if (i == 0) g_rowptr[NNODES] = E;
}

__global__ void k_scatter(const int* __restrict__ ei, int E) {
    int e = blockIdx.x * blockDim.x + threadIdx.x;
    if (e >= E) return;
    int s = ei[e];
    int d = ei[E + e];
    int pos = g_rowptr[d] + atomicAdd(&g_cursor[d], 1);
    g_col[pos] = s;
    g_wgt[pos] = g_dinv[s] * g_dinv[d];
}

// ---------------- WMMA FP16 GEMM (m16n16k16, fp32 accum, fp16 epilogue) -------
// g_H[M x BN] (fp16) = op(A)[M x K] @ B[K x BN]
// FUSE=false: A = Aext;  FUSE=true: A = relu(g_A*scale[k]+shift[k])
// fp16 operands have the same 10-bit mantissa as tf32; accumulate in fp32.
template <int BN, bool FUSE>
__global__ void __launch_bounds__(256)
k_gemm_wmma(const float* __restrict__ Aext, const float* __restrict__ B, int M, int K) {
    constexpr int BM = 128, BK = 32;
    constexpr int SAP = 40;              // half ldm, mult of 8
    constexpr int SBP = BN + 8;          // 136 or 72, mult of 8
    constexpr int WROWS = 4, WCOLS = 2;
    constexpr int WM = BM / WROWS;       // 32
    constexpr int WN = BN / WCOLS;       // 64 or 32
    constexpr int MT = WM / 16;          // 2
    constexpr int NT = WN / 16;          // 4 or 2
    constexpr int STG_LD = 24;           // fp32 staging ldm

    constexpr int SA_BYTES = BM * SAP * 2;          // 10240
    constexpr int SB_BYTES = BK * SBP * 2;          // 8704 or 4608
    constexpr int STG_BYTES = 8 * 16 * STG_LD * 4;  // 12288
    constexpr int SMEM_BYTES =
        (SA_BYTES + SB_BYTES) > STG_BYTES ? (SA_BYTES + SB_BYTES) : STG_BYTES;
    __shared__ __align__(16) char smem_raw[SMEM_BYTES];
    __half* sA = (__half*)smem_raw;
    __half* sB = (__half*)(smem_raw + SA_BYTES);

    const float* A = FUSE ? (const float*)g_A : Aext;   // device-side select

    const int tid = threadIdx.x;
    const int wid = tid >> 5;
    const int lane = tid & 31;
    const int wm = wid / WCOLS;
    const int wn = wid % WCOLS;
    const int row0 = blockIdx.x * BM;

    wmma::fragment<wmma::accumulator, 16, 16, 16, float> acc[MT][NT];
#pragma unroll
    for (int i = 0; i < MT; i++)
#pragma unroll
        for (int j = 0; j < NT; j++) wmma::fill_fragment(acc[i][j], 0.0f);

    constexpr int NPB = (BK * BN / 4) / 256;

    for (int kt = 0; kt < K; kt += BK) {
        // ---- load A tile (optional BN+ReLU fusion), cvt fp16 ----
#pragma unroll
        for (int p = 0; p < 4; p++) {
            int idx = tid + p * 256;
            int r = idx >> 3;
            int c4 = idx & 7;
            int gr = row0 + r;
            float4 v = make_float4(0.f, 0.f, 0.f, 0.f);
            if (gr < M) v = *(const float4*)(A + (size_t)gr * K + kt + c4 * 4);
            if (FUSE) {
                float4 sc = *(const float4*)(g_scale + kt + c4 * 4);
                float4 sh = *(const float4*)(g_shift + kt + c4 * 4);
                v.x = fmaxf(0.f, v.x * sc.x + sh.x);
                v.y = fmaxf(0.f, v.y * sc.y + sh.y);
                v.z = fmaxf(0.f, v.z * sc.z + sh.z);
                v.w = fmaxf(0.f, v.w * sc.w + sh.w);
            }
            __half2 h0 = __floats2half2_rn(v.x, v.y);
            __half2 h1 = __floats2half2_rn(v.z, v.w);
            *(uint2*)&sA[r * SAP + c4 * 4] =
                make_uint2(*(unsigned*)&h0, *(unsigned*)&h1);
        }
        // ---- load B tile, cvt fp16 ----
#pragma unroll
        for (int p = 0; p < NPB; p++) {
            int idx = tid + p * 256;
            int r = idx / (BN / 4);
            int c4 = idx % (BN / 4);
            float4 v = *(const float4*)(B + (size_t)(kt + r) * BN + c4 * 4);
            __half2 h0 = __floats2half2_rn(v.x, v.y);
            __half2 h1 = __floats2half2_rn(v.z, v.w);
            *(uint2*)&sB[r * SBP + c4 * 4] =
                make_uint2(*(unsigned*)&h0, *(unsigned*)&h1);
        }
        __syncthreads();

        // ---- mma: 2 K-steps of 16 (half the steps, half the LDS of tf32) ----
#pragma unroll
        for (int kk = 0; kk < BK; kk += 16) {
            wmma::fragment<wmma::matrix_a, 16, 16, 16, __half,
                           wmma::row_major> af[MT];
            wmma::fragment<wmma::matrix_b, 16, 16, 16, __half,
                           wmma::row_major> bf[NT];
#pragma unroll
            for (int mt = 0; mt < MT; mt++)
                wmma::load_matrix_sync(af[mt],
                    &sA[(wm * WM + mt * 16) * SAP + kk], SAP);
#pragma unroll
            for (int nt = 0; nt < NT; nt++)
                wmma::load_matrix_sync(bf[nt],
                    &sB[kk * SBP + wn * WN + nt * 16], SBP);
#pragma unroll
            for (int mt = 0; mt < MT; mt++)
#pragma unroll
                for (int nt = 0; nt < NT; nt++)
                    wmma::mma_sync(acc[mt][nt], af[mt], bf[nt], acc[mt][nt]);
        }
        __syncthreads();
    }

    // ---- epilogue: fragments -> fp32 smem staging (reuse whole buffer) -> fp16 ----
    float* stage = (float*)smem_raw + wid * (16 * STG_LD);
    const int r  = lane >> 1;            // 0..15
    const int c0 = (lane & 1) * 8;       // 0 or 8
#pragma unroll
    for (int mt = 0; mt < MT; mt++) {
#pragma unroll
        for (int nt = 0; nt < NT; nt++) {
            wmma::store_matrix_sync(stage, acc[mt][nt], STG_LD, wmma::mem_row_major);
            __syncwarp();
            int gr = row0 + wm * WM + mt * 16 + r;
            if (gr < M) {
                int gc = wn * WN + nt * 16 + c0;
                __half hbuf[8];
#pragma unroll
                for (int q = 0; q < 8; q++)
                    hbuf[q] = __float2half(stage[r * STG_LD + c0 + q]);
                *(uint4*)(g_H + (size_t)gr * BN + gc) = *(uint4*)hbuf;
            }
            __syncwarp();
        }
    }
}

// ---------------- grid-stride aggregation + register-fused BN statistics ----
// 1 warp per node; H gathered in fp16, fp32 accumulate.
template <int D, bool STATS, bool EXT_OUT>
__global__ void __launch_bounds__(256)
k_agg(const float* __restrict__ bias, float* __restrict__ out_ext) {
    constexpr int VEC = D / 32;          // 4 (D=128) or 2 (D=64)
    __shared__ float bsum[STATS ? D : 1];
    __shared__ float bsq [STATS ? D : 1];

    const int tid = threadIdx.x;
    if (STATS) {
        if (tid < D) { bsum[tid] = 0.f; bsq[tid] = 0.f; }
        __syncthreads();
    }

    const int lane = tid & 31;
    const int base = lane * VEC;
    const int warpsPerBlock = 256 >> 5;  // 8
    int gw = blockIdx.x * warpsPerBlock + (tid >> 5);
    const int stride = gridDim.x * warpsPerBlock;
    const __half* H = g_H;
    float* out = EXT_OUT ? out_ext : (float*)g_A;

    float bv[VEC];
#pragma unroll
    for (int q = 0; q < VEC; q++) bv[q] = bias[base + q];

    float sm[VEC], sq[VEC];
#pragma unroll
    for (int q = 0; q < VEC; q++) { sm[q] = 0.f; sq[q] = 0.f; }

    for (int node = gw; node < NNODES; node += stride) {
        float di = g_dinv[node];
        float self = di * di;

        if constexpr (VEC == 4) {
            uint2 hr = *(const uint2*)(H + (size_t)node * D + base);
            float2 ha = __half22float2(*(__half2*)&hr.x);
            float2 hb = __half22float2(*(__half2*)&hr.y);
            float a0 = bv[0] + self * ha.x;
            float a1 = bv[1] + self * ha.y;
            float a2 = bv[2] + self * hb.x;
            float a3 = bv[3] + self * hb.y;
            float b0 = 0.f, b1 = 0.f, b2 = 0.f, b3 = 0.f;

            int j  = g_rowptr[node];
            int je = g_rowptr[node + 1];
            for (; j + 1 < je; j += 2) {
                int   s0 = __ldg(&g_col[j]),  s1 = __ldg(&g_col[j + 1]);
                float w0 = __ldg(&g_wgt[j]),  w1 = __ldg(&g_wgt[j + 1]);
                uint2 r0 = *(const uint2*)(H + (size_t)s0 * D + base);
                uint2 r1 = *(const uint2*)(H + (size_t)s1 * D + base);
                float2 x0a = __half22float2(*(__half2*)&r0.x);
                float2 x0b = __half22float2(*(__half2*)&r0.y);
                float2 x1a = __half22float2(*(__half2*)&r1.x);
                float2 x1b = __half22float2(*(__half2*)&r1.y);
                a0 += w0 * x0a.x; a1 += w0 * x0a.y; a2 += w0 * x0b.x; a3 += w0 * x0b.y;
                b0 += w1 * x1a.x; b1 += w1 * x1a.y; b2 += w1 * x1b.x; b3 += w1 * x1b.y;
            }
            if (j < je) {
                int   s0 = __ldg(&g_col[j]);
                float w0 = __ldg(&g_wgt[j]);
                uint2 r0 = *(const uint2*)(H + (size_t)s0 * D + base);
                float2 x0a = __half22float2(*(__half2*)&r0.x);
                float2 x0b = __half22float2(*(__half2*)&r0.y);
                a0 += w0 * x0a.x; a1 += w0 * x0a.y; a2 += w0 * x0b.x; a3 += w0 * x0b.y;
            }
            float v0 = a0 + b0, v1 = a1 + b1, v2 = a2 + b2, v3 = a3 + b3;
            *(float4*)(out + (size_t)node * D + base) = make_float4(v0, v1, v2, v3);
            if (STATS) {
                sm[0] += v0; sm[1] += v1; sm[2] += v2; sm[3] += v3;
                sq[0] += v0 * v0; sq[1] += v1 * v1;
                sq[2] += v2 * v2; sq[3] += v3 * v3;
            }
        } else {
            uint32_t hr = *(const uint32_t*)(H + (size_t)node * D + base);
            float2 ha = __half22float2(*(__half2*)&hr);
            float a0 = bv[0] + self * ha.x;
            float a1 = bv[1] + self * ha.y;
            float b0 = 0.f, b1 = 0.f;

            int j  = g_rowptr[node];
            int je = g_rowptr[node + 1];
            for (; j + 1 < je; j += 2) {
                int   s0 = __ldg(&g_col[j]),  s1 = __ldg(&g_col[j + 1]);
                float w0 = __ldg(&g_wgt[j]),  w1 = __ldg(&g_wgt[j + 1]);
                uint32_t r0 = *(const uint32_t*)(H + (size_t)s0 * D + base);
                uint32_t r1 = *(const uint32_t*)(H + (size_t)s1 * D + base);
                float2 x0 = __half22float2(*(__half2*)&r0);
                float2 x1 = __half22float2(*(__half2*)&r1);
                a0 += w0 * x0.x; a1 += w0 * x0.y;
                b0 += w1 * x1.x; b1 += w1 * x1.y;
            }
            if (j < je) {
                int   s0 = __ldg(&g_col[j]);
                float w0 = __ldg(&g_wgt[j]);
                uint32_t r0 = *(const uint32_t*)(H + (size_t)s0 * D + base);
                float2 x0 = __half22float2(*(__half2*)&r0);
                a0 += w0 * x0.x; a1 += w0 * x0.y;
            }
            float v0 = a0 + b0, v1 = a1 + b1;
            *(float2*)(out + (size_t)node * D + base) = make_float2(v0, v1);
            if (STATS) {
                sm[0] += v0; sm[1] += v1;
                sq[0] += v0 * v0; sq[1] += v1 * v1;
            }
        }
    }

    if (STATS) {
#pragma unroll
        for (int q = 0; q < VEC; q++) {
            atomicAdd(&bsum[base + q], sm[q]);
            atomicAdd(&bsq [base + q], sq[q]);
        }
        __syncthreads();
        if (tid < D) {
            atomicAdd(&g_stats[tid],     bsum[tid]);
            atomicAdd(&g_stats[D + tid], bsq[tid]);
        }
    }
}

// ---------------- BatchNorm finalize (also re-zeroes stats for next layer) ----
__global__ void k_bnfinal(const float* __restrict__ g, const float* __restrict__ bt) {
    int t = threadIdx.x;
    if (t >= DH) return;
    float invN = 1.0f / (float)NNODES;
    float mu = g_stats[t] * invN;
    float var = g_stats[DH + t] * invN - mu * mu;
    float r = rsqrtf(var + BN_EPS);
    float a = g[t] * r;
    g_scale[t] = a;
    g_shift[t] = bt[t] - mu * a;
    g_stats[t] = 0.f;
    g_stats[DH + t] = 0.f;
}

// ---------------- launcher ----------------
extern "C" void kernel_launch(void* const* d_in, const int* in_sizes, int n_in,
                              void* d_out, int out_size) {
    const float* x   = (const float*)d_in[0];
    const int*   ei  = (const int*)d_in[1];
    const float* W1  = (const float*)d_in[2];
    const float* b1  = (const float*)d_in[3];
    const float* g1  = (const float*)d_in[4];
    const float* bt1 = (const float*)d_in[5];
    const float* W2  = (const float*)d_in[6];
    const float* b2  = (const float*)d_in[7];
    const float* g2  = (const float*)d_in[8];
    const float* bt2 = (const float*)d_in[9];
    const float* W3  = (const float*)d_in[10];
    const float* b3  = (const float*)d_in[11];
    float* out = (float*)d_out;

    const int E = in_sizes[1] / 2;
    const int M = in_sizes[0] / DIN;

    const int TB = 256;
    dim3 nodeGrid((NNODES + TB - 1) / TB);
    dim3 edgeGrid((E + TB - 1) / TB);
    dim3 gemmGrid((M + 127) / 128);

    // fork/join resources (host-side; created per call, leaked — kernel_launch
    // runs only a handful of times; graph replays re-run GPU work only)
    cudaStream_t s2;
    cudaStreamCreateWithFlags(&s2, cudaStreamNonBlocking);
    cudaEvent_t e0, e1;
    cudaEventCreateWithFlags(&e0, cudaEventDisableTiming);
    cudaEventCreateWithFlags(&e1, cudaEventDisableTiming);

    // ---- fork: GEMM1 (depends only on x/W1) runs on s2, CSR build on default ----
    cudaEventRecord(e0, 0);
    cudaStreamWaitEvent(s2, e0, 0);
    k_gemm_wmma<DH, false><<<gemmGrid, 256, 0, s2>>>(x, W1, M, DIN);
    cudaEventRecord(e1, s2);

    // --- graph normalization + CSR build (default stream, overlaps GEMM1) ---
    k_zero_node_ints<<<nodeGrid, TB>>>();
    k_count_deg<<<edgeGrid, TB>>>(ei, E);
    k_dinv<<<nodeGrid, TB>>>();
    k_scan1<<<NB_SCAN, 256>>>();
    k_scan2<<<1, 512>>>();
    k_scan3<<<NB_SCAN, 256>>>(E);
    k_scatter<<<edgeGrid, TB>>>(ei, E);

    // ---- join: layer-1 agg needs both CSR and GEMM1 ----
    cudaStreamWaitEvent(0, e1, 0);

    // --- layer 1 ---
    k_agg<DH, true, false><<<AGG_BLOCKS, 256>>>(b1, nullptr);
    k_bnfinal<<<1, DH>>>(g1, bt1);

    // --- layer 2 (BN1+ReLU fused into GEMM A-load) ---
    k_gemm_wmma<DH, true><<<gemmGrid, 256>>>(nullptr, W2, M, DH);
    k_agg<DH, true, false><<<AGG_BLOCKS, 256>>>(b2, nullptr);
    k_bnfinal<<<1, DH>>>(g2, bt2);

    // --- layer 3 (BN2+ReLU fused into GEMM A-load) ---
    k_gemm_wmma<DOUT, true><<<gemmGrid, 256>>>(nullptr, W3, M, DH);
    k_agg<DOUT, false, true><<<AGG_BLOCKS, 256>>>(b3, out);
}